// round 1
// baseline (speedup 1.0000x reference)
#include <cuda_runtime.h>
#include <math.h>

// Problem sizes (fixed)
#define BB   64
#define TT   512
#define EE   1024
#define HH   1024
#define NG   4096              // 4 gates * H
#define AF_ELEMS (64ULL*512ULL*1024ULL)

typedef unsigned long long u64;

// Scratch: GX[t][n][b]  (gate preactivations from x-projection + bias), and c state.
__device__ float g_gx[(size_t)TT * NG * BB];   // 512 MB, static device scratch (allowed)
__device__ float g_c[BB * HH];

__device__ __forceinline__ void fma2(u64& d, u64 a, u64 b) {
    asm("fma.rn.f32x2 %0, %1, %2, %0;" : "+l"(d) : "l"(a), "l"(b));
}
__device__ __forceinline__ float2 upk(u64 v) {
    float2 f; asm("mov.b64 {%0, %1}, %2;" : "=f"(f.x), "=f"(f.y) : "l"(v)); return f;
}
__device__ __forceinline__ u64 pkdup(float v) {
    u64 r; asm("mov.b64 %0, {%1, %1};" : "=l"(r) : "f"(v)); return r;
}
__device__ __forceinline__ float sigf(float x) { return 1.0f / (1.0f + expf(-x)); }

// ---------------------------------------------------------------------------
// Phase 1: GX[t][n][b] = sum_k x[b][t][k] * W_g[h][1024+k] + bias_g[h]
//   n = gate*1024 + h.  Grid: (32 n-blocks of 128, 512 t).  BM=64(b) BN=128(n) BK=16.
//   256 threads; thread tile 4(b) x 8(n), f32x2-packed along n-pairs.
// ---------------------------------------------------------------------------
__global__ __launch_bounds__(256) void gx_kernel(
    const float* __restrict__ x,
    const float* __restrict__ wc, const float* __restrict__ wu,
    const float* __restrict__ wf, const float* __restrict__ wo,
    const float* __restrict__ bc, const float* __restrict__ bu,
    const float* __restrict__ bf, const float* __restrict__ bo)
{
    __shared__ u64   As2[16 * 64];    // [k][b], each entry = (a,a) duplicated pair
    __shared__ float Bs[16 * 128];    // [k][nloc]

    const int tid  = threadIdx.x;
    const int gate = blockIdx.x >> 3;            // 8 n-blocks per gate
    const int hblk = (blockIdx.x & 7) * 128;     // h offset within gate
    const int t0   = blockIdx.y;

    const float* wgate = (gate == 0) ? wc : (gate == 1) ? wu : (gate == 2) ? wf : wo;
    const float* bgate = (gate == 0) ? bc : (gate == 1) ? bu : (gate == 2) ? bf : bo;

    const int tn = tid & 15;          // n-group: nloc = tn*8 .. +7
    const int tb = tid >> 4;          // b-group: b = tb*4 .. +3

    u64 acc[4][4];                    // [bi][npair], packed (n_even, n_odd)
    #pragma unroll
    for (int i = 0; i < 4; i++)
        #pragma unroll
        for (int p = 0; p < 4; p++) acc[i][p] = 0ULL;

    // Loader mappings (fixed per thread)
    const int arow = tid >> 2, akq = tid & 3;          // A: 64 rows x (4 thr * float4)
    const int brow = tid >> 1, bkq = tid & 1;          // B: 128 rows x (2 thr * 2*float4)
    const float* xrow = x + (size_t)arow * (TT * EE) + (size_t)t0 * EE;
    const float* wrow = wgate + (size_t)(hblk + brow) * 2048 + 1024;

    for (int k0 = 0; k0 < 1024; k0 += 16) {
        float4 va  = *(const float4*)(xrow + k0 + akq * 4);
        float4 vb0 = *(const float4*)(wrow + k0 + bkq * 8);
        float4 vb1 = *(const float4*)(wrow + k0 + bkq * 8 + 4);
        __syncthreads();   // previous iteration's compute done before overwrite
        {
            float vs[4] = {va.x, va.y, va.z, va.w};
            #pragma unroll
            for (int i = 0; i < 4; i++)
                As2[(akq * 4 + i) * 64 + arow] = pkdup(vs[i]);
        }
        {
            float v0[4] = {vb0.x, vb0.y, vb0.z, vb0.w};
            float v1[4] = {vb1.x, vb1.y, vb1.z, vb1.w};
            #pragma unroll
            for (int i = 0; i < 4; i++) {
                Bs[(bkq * 8 + i) * 128 + brow]     = v0[i];
                Bs[(bkq * 8 + 4 + i) * 128 + brow] = v1[i];
            }
        }
        __syncthreads();
        #pragma unroll
        for (int k = 0; k < 16; k++) {
            ulonglong2 aa0 = *(const ulonglong2*)&As2[k * 64 + tb * 4];
            ulonglong2 aa1 = *(const ulonglong2*)&As2[k * 64 + tb * 4 + 2];
            const float* bp = &Bs[k * 128 + tn * 8];
            ulonglong2 bb0 = *(const ulonglong2*)(bp);
            ulonglong2 bb1 = *(const ulonglong2*)(bp + 4);
            u64 a_[4] = {aa0.x, aa0.y, aa1.x, aa1.y};
            u64 b_[4] = {bb0.x, bb0.y, bb1.x, bb1.y};
            #pragma unroll
            for (int bi = 0; bi < 4; bi++)
                #pragma unroll
                for (int np = 0; np < 4; np++)
                    fma2(acc[bi][np], a_[bi], b_[np]);
        }
    }

    // Epilogue: add bias, store GX[t][n][b]
    #pragma unroll
    for (int bi = 0; bi < 4; bi++) {
        const int bb2 = tb * 4 + bi;
        #pragma unroll
        for (int np = 0; np < 4; np++) {
            const int hloc = hblk + tn * 8 + np * 2;       // h of even lane
            const int n    = gate * 1024 + hloc;
            float2 v = upk(acc[bi][np]);
            v.x += bgate[hloc];
            v.y += bgate[hloc + 1];
            g_gx[((size_t)t0 * NG + n) * BB + bb2]     = v.x;
            g_gx[((size_t)t0 * NG + n + 1) * BB + bb2] = v.y;
        }
    }
}

// ---------------------------------------------------------------------------
// Phase 2: one kernel per timestep.
//   CTA c owns hidden units h in [c*8, c*8+8), all 4 gates.  256 threads:
//   b = tid&63, j = tid>>6 -> units h = hbase + j*2 + {0,1}.
//   pre[g][h] = sum_k a_prev[b][k] * W_g[h][k]  (K streamed in 64-chunks via SMEM)
//   then the elementwise LSTM update; a written straight into out (= a_f).
// ---------------------------------------------------------------------------
__global__ __launch_bounds__(256) void lstm_step(
    int t,
    const float* __restrict__ a_prev, long long a_stride,
    const float* __restrict__ wc, const float* __restrict__ wu,
    const float* __restrict__ wf, const float* __restrict__ wo,
    const float* __restrict__ c0,
    float* __restrict__ out)
{
    __shared__ float ws[32 * 68];     // 32 weight rows x 64 k (stride 68 floats)
    __shared__ u64   a2s[32 * 65];    // 32 k-pairs x 64 b (stride 65 u64)

    const int tid   = threadIdx.x;
    const int b     = tid & 63;
    const int j     = tid >> 6;                  // 0..3
    const int hbase = blockIdx.x * 8;

    // Hoisted loader mappings
    // weights: idx = tid + i*256 -> r = idx>>4 (0..31), kq = idx&15
    const float* wptr[2];
    #pragma unroll
    for (int i = 0; i < 2; i++) {
        const int idx = tid + i * 256;
        const int r = idx >> 4;
        const int g = r >> 3, hh = r & 7;
        const float* wsel = (g == 0) ? wc : (g == 1) ? wu : (g == 2) ? wf : wo;
        wptr[i] = wsel + (size_t)(hbase + hh) * 2048 + (idx & 15) * 4;
    }
    // a: idx = tid + i*256 -> bb = idx>>5 (0..63), k2 = idx&31
    const float* aptr[8];
    #pragma unroll
    for (int i = 0; i < 8; i++) {
        const int idx = tid + i * 256;
        aptr[i] = a_prev + (size_t)(idx >> 5) * a_stride + (idx & 31) * 2;
    }

    u64 acc[4][2];   // [gate][h2], packed over (k even, k odd)
    #pragma unroll
    for (int g = 0; g < 4; g++) { acc[g][0] = 0ULL; acc[g][1] = 0ULL; }

    for (int k0 = 0; k0 < 1024; k0 += 64) {
        float4 wv[2];
        #pragma unroll
        for (int i = 0; i < 2; i++) wv[i] = *(const float4*)(wptr[i] + k0);
        u64 av[8];
        #pragma unroll
        for (int i = 0; i < 8; i++) av[i] = *(const u64*)(aptr[i] + k0);

        __syncthreads();   // previous chunk's compute done
        #pragma unroll
        for (int i = 0; i < 2; i++) {
            const int idx = tid + i * 256;
            *(float4*)(ws + (idx >> 4) * 68 + (idx & 15) * 4) = wv[i];
        }
        #pragma unroll
        for (int i = 0; i < 8; i++) {
            const int idx = tid + i * 256;
            a2s[(idx & 31) * 65 + (idx >> 5)] = av[i];
        }
        __syncthreads();

        #pragma unroll
        for (int k2 = 0; k2 < 32; k2 += 2) {
            const u64 a0v = a2s[k2 * 65 + b];
            const u64 a1v = a2s[(k2 + 1) * 65 + b];
            #pragma unroll
            for (int g = 0; g < 4; g++) {
                #pragma unroll
                for (int h2 = 0; h2 < 2; h2++) {
                    const int r = g * 8 + j * 2 + h2;
                    const ulonglong2 w2 = *(const ulonglong2*)(ws + r * 68 + k2 * 2);
                    fma2(acc[g][h2], a0v, w2.x);
                    fma2(acc[g][h2], a1v, w2.y);
                }
            }
        }
    }

    // Epilogue
    const int h0 = hbase + j * 2;
    float pre[4][2];
    #pragma unroll
    for (int g = 0; g < 4; g++)
        #pragma unroll
        for (int h2 = 0; h2 < 2; h2++) {
            const float2 v = upk(acc[g][h2]);
            const int n = g * 1024 + h0 + h2;
            pre[g][h2] = v.x + v.y + g_gx[((size_t)t * NG + n) * BB + b];
        }

    const float* csrc = (t == 0) ? c0 : g_c;
    #pragma unroll
    for (int h2 = 0; h2 < 2; h2++) {
        const int h = h0 + h2;
        const float cand = tanhf(pre[0][h2]);
        const float gu   = sigf(pre[1][h2]);
        const float gf   = sigf(pre[2][h2]);
        const float go   = sigf(pre[3][h2]);
        const float cold = csrc[b * HH + h];
        const float c1   = gu * cand + gf * cold;
        const float a1   = go * tanhf(c1);
        g_c[b * HH + h] = c1;
        out[(size_t)b * (TT * HH) + (size_t)t * HH + h] = a1;
        if (t == TT - 1) {
            out[AF_ELEMS + (size_t)b * HH + h]            = a1;   // a_T
            out[AF_ELEMS + BB * HH + (size_t)b * HH + h]  = c1;   // c_T
        }
    }
}

// ---------------------------------------------------------------------------
extern "C" void kernel_launch(void* const* d_in, const int* in_sizes, int n_in,
                              void* d_out, int out_size) {
    (void)in_sizes; (void)n_in; (void)out_size;
    const float* x  = (const float*)d_in[0];
    const float* a0 = (const float*)d_in[1];
    const float* c0 = (const float*)d_in[2];
    const float* wc = (const float*)d_in[3];
    const float* wu = (const float*)d_in[4];
    const float* wf = (const float*)d_in[5];
    const float* wo = (const float*)d_in[6];
    const float* bc = (const float*)d_in[7];
    const float* bu = (const float*)d_in[8];
    const float* bf = (const float*)d_in[9];
    const float* bo = (const float*)d_in[10];
    float* out = (float*)d_out;

    // Phase 1: x-projection for all timesteps (parallel GEMM)
    dim3 g1(32, TT);
    gx_kernel<<<g1, 256>>>(x, wc, wu, wf, wo, bc, bu, bf, bo);

    // Phase 2: sequential recurrence, one launch per step (graph-captured)
    for (int t = 0; t < TT; t++) {
        const float* ap = (t == 0) ? a0 : (out + (size_t)(t - 1) * HH);
        const long long stride = (t == 0) ? (long long)HH : (long long)(TT * HH);
        lstm_step<<<128, 256>>>(t, ap, stride, wc, wu, wf, wo, c0, out);
    }
}

// round 3
// speedup vs baseline: 1.2963x; 1.2963x over previous
#include <cuda_runtime.h>
#include <math.h>

// Problem sizes (fixed)
#define BB   64
#define TT   512
#define EE   1024
#define HH   1024
#define NG   4096              // 4 gates * H
#define AF_ELEMS (64ULL*512ULL*1024ULL)
#define NCTA 128

typedef unsigned long long u64;
typedef unsigned int u32;

// Static device scratch (allocation-free)
__device__ float g_gx[(size_t)TT * NG * BB];   // 512 MB: GX[t][n][b]
__device__ u64   g_a2[2][BB * 512];            // a state, double-buffered by step parity
__device__ u32   g_bar[TT];                    // monotonic per-step barrier counters

__device__ __forceinline__ void fma2(u64& d, u64 a, u64 b) {
    asm("fma.rn.f32x2 %0, %1, %2, %0;" : "+l"(d) : "l"(a), "l"(b));
}
__device__ __forceinline__ u64 addf2(u64 a, u64 b) {
    u64 r; asm("add.rn.f32x2 %0, %1, %2;" : "=l"(r) : "l"(a), "l"(b)); return r;
}
__device__ __forceinline__ float2 upk(u64 v) {
    float2 f; asm("mov.b64 {%0, %1}, %2;" : "=f"(f.x), "=f"(f.y) : "l"(v)); return f;
}
__device__ __forceinline__ u64 pkdup(float v) {
    u64 r; asm("mov.b64 %0, {%1, %1};" : "=l"(r) : "f"(v)); return r;
}
__device__ __forceinline__ float sigf(float x) { return 1.0f / (1.0f + expf(-x)); }

// ---------------------------------------------------------------------------
// Phase 1 (unchanged, validated): GX[t][n][b] = x[b][t][:] . W_g[h][1024:] + bias
// ---------------------------------------------------------------------------
__global__ __launch_bounds__(256) void gx_kernel(
    const float* __restrict__ x,
    const float* __restrict__ wc, const float* __restrict__ wu,
    const float* __restrict__ wf, const float* __restrict__ wo,
    const float* __restrict__ bc, const float* __restrict__ bu,
    const float* __restrict__ bf, const float* __restrict__ bo)
{
    __shared__ u64   As2[16 * 64];
    __shared__ float Bs[16 * 128];

    const int tid  = threadIdx.x;
    const int gate = blockIdx.x >> 3;
    const int hblk = (blockIdx.x & 7) * 128;
    const int t0   = blockIdx.y;

    const float* wgate = (gate == 0) ? wc : (gate == 1) ? wu : (gate == 2) ? wf : wo;
    const float* bgate = (gate == 0) ? bc : (gate == 1) ? bu : (gate == 2) ? bf : bo;

    const int tn = tid & 15;
    const int tb = tid >> 4;

    u64 acc[4][4];
    #pragma unroll
    for (int i = 0; i < 4; i++)
        #pragma unroll
        for (int p = 0; p < 4; p++) acc[i][p] = 0ULL;

    const int arow = tid >> 2, akq = tid & 3;
    const int brow = tid >> 1, bkq = tid & 1;
    const float* xrow = x + (size_t)arow * (TT * EE) + (size_t)t0 * EE;
    const float* wrow = wgate + (size_t)(hblk + brow) * 2048 + 1024;

    for (int k0 = 0; k0 < 1024; k0 += 16) {
        float4 va  = *(const float4*)(xrow + k0 + akq * 4);
        float4 vb0 = *(const float4*)(wrow + k0 + bkq * 8);
        float4 vb1 = *(const float4*)(wrow + k0 + bkq * 8 + 4);
        __syncthreads();
        {
            float vs[4] = {va.x, va.y, va.z, va.w};
            #pragma unroll
            for (int i = 0; i < 4; i++)
                As2[(akq * 4 + i) * 64 + arow] = pkdup(vs[i]);
        }
        {
            float v0[4] = {vb0.x, vb0.y, vb0.z, vb0.w};
            float v1[4] = {vb1.x, vb1.y, vb1.z, vb1.w};
            #pragma unroll
            for (int i = 0; i < 4; i++) {
                Bs[(bkq * 8 + i) * 128 + brow]     = v0[i];
                Bs[(bkq * 8 + 4 + i) * 128 + brow] = v1[i];
            }
        }
        __syncthreads();
        #pragma unroll
        for (int k = 0; k < 16; k++) {
            ulonglong2 aa0 = *(const ulonglong2*)&As2[k * 64 + tb * 4];
            ulonglong2 aa1 = *(const ulonglong2*)&As2[k * 64 + tb * 4 + 2];
            const float* bp = &Bs[k * 128 + tn * 8];
            ulonglong2 bb0 = *(const ulonglong2*)(bp);
            ulonglong2 bb1 = *(const ulonglong2*)(bp + 4);
            u64 a_[4] = {aa0.x, aa0.y, aa1.x, aa1.y};
            u64 b_[4] = {bb0.x, bb0.y, bb1.x, bb1.y};
            #pragma unroll
            for (int bi = 0; bi < 4; bi++)
                #pragma unroll
                for (int np = 0; np < 4; np++)
                    fma2(acc[bi][np], a_[bi], b_[np]);
        }
    }

    #pragma unroll
    for (int bi = 0; bi < 4; bi++) {
        const int bb2 = tb * 4 + bi;
        #pragma unroll
        for (int np = 0; np < 4; np++) {
            const int hloc = hblk + tn * 8 + np * 2;
            const int n    = gate * 1024 + hloc;
            float2 v = upk(acc[bi][np]);
            v.x += bgate[hloc];
            v.y += bgate[hloc + 1];
            g_gx[((size_t)t0 * NG + n) * BB + bb2]     = v.x;
            g_gx[((size_t)t0 * NG + n + 1) * BB + bb2] = v.y;
        }
    }
}

// ---------------------------------------------------------------------------
// Phase 2: PERSISTENT recurrence kernel.
//   128 CTAs x 256 threads, all co-resident. CTA owns h in [blk*8, blk*8+8),
//   all 4 gates -> 32 weight rows x 1024 k, kept in SMEM for all 512 steps.
//   Warp = (khalf, j): khalf splits K (0..511 / 512..1023), j picks h-pair.
//   Thread tile: 8 rows (4 gates x 2 h) x 2 batches (lane, lane+32), k packed
//   as f32x2 pairs. c-state lives in registers. Grid barrier between steps.
//   K covered in 8 chunks x 32 k2-pairs per half  (8*32*2 k2 * 2 halves = 1024 k).
// SMEM (dynamic, u64 units):
//   [0, 16384)          weights ws2[row][k2]           (128 KB)
//   [16384, 24704)      a-chunks: 4 bufs of 32x65      (66.5 KB)
// ---------------------------------------------------------------------------
#define SMEM_U64 24704
#define ABUF(half, par) (16384 + ((half)*2 + (par)) * 2080)

__global__ __launch_bounds__(256, 1) void lstm_persist(
    const float* __restrict__ a0, const float* __restrict__ c0,
    const float* __restrict__ wc, const float* __restrict__ wu,
    const float* __restrict__ wf, const float* __restrict__ wo,
    float* __restrict__ out)
{
    extern __shared__ u64 sm[];
    u64* ws2 = sm;

    const int tid   = threadIdx.x;
    const int lane  = tid & 31;
    const int wid   = tid >> 5;
    const int j     = wid & 3;          // h-pair within CTA
    const int khalf = wid >> 2;         // K split half
    const int hbase = blockIdx.x * 8;
    const int b0 = lane, b1 = lane + 32;
    const int h0 = hbase + j * 2;

    // ---- one-time: weights -> SMEM (recurrent half: cols [0,1024)) ----
    for (int idx = tid; idx < 32 * 512; idx += 256) {
        const int r = idx >> 9, k2 = idx & 511;
        const int g = r >> 3, hh = r & 7;
        const float* wsel = (g == 0) ? wc : (g == 1) ? wu : (g == 2) ? wf : wo;
        ws2[idx] = ((const u64*)(wsel + (size_t)(hbase + hh) * 2048))[k2];
    }

    // ---- c-state in registers (khalf0 threads own the epilogue) ----
    float creg[2][2];   // [h2][bi]
    if (khalf == 0) {
        #pragma unroll
        for (int h2 = 0; h2 < 2; h2++) {
            creg[h2][0] = c0[b0 * HH + h0 + h2];
            creg[h2][1] = c0[b1 * HH + h0 + h2];
        }
    }

    // per-row weight bases (invariant across steps)
    const u64* wrp[8];
    #pragma unroll
    for (int r = 0; r < 8; r++) {
        const int g = r >> 1, h2 = r & 1;
        wrp[r] = ws2 + (size_t)(g * 8 + j * 2 + h2) * 512 + khalf * 256;
    }
    __syncthreads();

    for (int t = 0; t < TT; t++) {
        const u64* asrc = (t == 0) ? (const u64*)a0 : g_a2[t & 1];

        // GX prefetch (streaming; full-step slack before use)
        float gxv[16];
        if (khalf == 0) {
            const float* gxt = g_gx + (size_t)t * NG * BB;
            #pragma unroll
            for (int g = 0; g < 4; g++)
                #pragma unroll
                for (int h2 = 0; h2 < 2; h2++) {
                    const int n = g * 1024 + h0 + h2;
                    gxv[(g * 2 + h2) * 2 + 0] = __ldcs(&gxt[n * BB + b0]);
                    gxv[(g * 2 + h2) * 2 + 1] = __ldcs(&gxt[n * BB + b1]);
                }
        }

        // ---- prologue: stage chunk0 (both halves) into buf par0, ldg chunk1 ----
        u64 stage[16];
        #pragma unroll
        for (int v = 0; v < 16; v++) {
            const int idx = tid + v * 256;
            const int k2c = idx & 31, b = (idx >> 5) & 63, half = idx >> 11;
            stage[v] = asrc[(size_t)b * 512 + half * 256 + k2c];
        }
        #pragma unroll
        for (int v = 0; v < 16; v++) {
            const int idx = tid + v * 256;
            const int k2c = idx & 31, b = (idx >> 5) & 63, half = idx >> 11;
            sm[ABUF(half, 0) + k2c * 65 + b] = stage[v];
        }
        #pragma unroll
        for (int v = 0; v < 16; v++) {
            const int idx = tid + v * 256;
            const int k2c = idx & 31, b = (idx >> 5) & 63, half = idx >> 11;
            stage[v] = asrc[(size_t)b * 512 + half * 256 + 32 + k2c];
        }
        __syncthreads();

        u64 acc[8][2];
        #pragma unroll
        for (int r = 0; r < 8; r++) { acc[r][0] = 0ULL; acc[r][1] = 0ULL; }

        // 8 chunks of 32 k2-pairs cover the full 256 k2 of this K-half
        for (int i = 0; i < 8; i++) {
            // STS chunk i+1 (parity (i+1)&1) — prev reader of that parity is done
            if (i < 7) {
                #pragma unroll
                for (int v = 0; v < 16; v++) {
                    const int idx = tid + v * 256;
                    const int k2c = idx & 31, b = (idx >> 5) & 63, half = idx >> 11;
                    sm[ABUF(half, (i + 1) & 1) + k2c * 65 + b] = stage[v];
                }
            }
            // LDG chunk i+2 — a whole compute phase of latency slack
            if (i < 6) {
                #pragma unroll
                for (int v = 0; v < 16; v++) {
                    const int idx = tid + v * 256;
                    const int k2c = idx & 31, b = (idx >> 5) & 63, half = idx >> 11;
                    stage[v] = asrc[(size_t)b * 512 + half * 256 + (i + 2) * 32 + k2c];
                }
            }
            // compute 32 k2 (64 k) on buf parity i&1
            const u64* ab = sm + ABUF(khalf, i & 1);
            const int koff = i * 32;
            #pragma unroll
            for (int q = 0; q < 16; q++) {
                const int k2 = 2 * q;
                const u64 a00 = ab[k2 * 65 + b0];
                const u64 a01 = ab[k2 * 65 + b1];
                const u64 a10 = ab[(k2 + 1) * 65 + b0];
                const u64 a11 = ab[(k2 + 1) * 65 + b1];
                #pragma unroll
                for (int r = 0; r < 8; r++) {
                    const ulonglong2 wv = *(const ulonglong2*)&wrp[r][koff + k2];
                    fma2(acc[r][0], a00, wv.x);
                    fma2(acc[r][1], a01, wv.x);
                    fma2(acc[r][0], a10, wv.y);
                    fma2(acc[r][1], a11, wv.y);
                }
            }
            __syncthreads();
        }

        // ---- k-split reduction (khalf1 -> smem, reuse a-buffer region) ----
        u64* red = sm + 16384;
        if (khalf == 1) {
            #pragma unroll
            for (int r = 0; r < 8; r++) {
                red[(j * 32 + lane) * 16 + r * 2 + 0] = acc[r][0];
                red[(j * 32 + lane) * 16 + r * 2 + 1] = acc[r][1];
            }
        }
        __syncthreads();

        if (khalf == 0) {
            float pre[4][2][2];   // [gate][h2][bi]
            #pragma unroll
            for (int r = 0; r < 8; r++) {
                const int g = r >> 1, h2 = r & 1;
                #pragma unroll
                for (int bi = 0; bi < 2; bi++) {
                    const u64 s = addf2(acc[r][bi],
                                        red[(j * 32 + lane) * 16 + r * 2 + bi]);
                    const float2 v = upk(s);
                    pre[g][h2][bi] = v.x + v.y + gxv[r * 2 + bi];
                }
            }
            float a1[2][2], c1[2][2];
            #pragma unroll
            for (int h2 = 0; h2 < 2; h2++)
                #pragma unroll
                for (int bi = 0; bi < 2; bi++) {
                    const float cand = tanhf(pre[0][h2][bi]);
                    const float gu   = sigf(pre[1][h2][bi]);
                    const float gf   = sigf(pre[2][h2][bi]);
                    const float go   = sigf(pre[3][h2][bi]);
                    const float cc   = gu * cand + gf * creg[h2][bi];
                    c1[h2][bi] = cc;
                    a1[h2][bi] = go * tanhf(cc);
                    creg[h2][bi] = cc;
                }
            const int bs[2] = {b0, b1};
            #pragma unroll
            for (int bi = 0; bi < 2; bi++) {
                const int b = bs[bi];
                float2 av; av.x = a1[0][bi]; av.y = a1[1][bi];
                *(float2*)(out + (size_t)b * (TT * HH) + (size_t)t * HH + h0) = av;
                *(float2*)&g_a2[(t + 1) & 1][(size_t)b * 512 + (h0 >> 1)] = av;
                if (t == TT - 1) {
                    *(float2*)(out + AF_ELEMS + (size_t)b * HH + h0) = av;
                    float2 cv; cv.x = c1[0][bi]; cv.y = c1[1][bi];
                    *(float2*)(out + AF_ELEMS + (size_t)BB * HH + (size_t)b * HH + h0) = cv;
                }
            }
        }

        // ---- grid barrier (monotonic counters: graph-replay safe) ----
        if (t < TT - 1) {
            __threadfence();
            __syncthreads();
            if (tid == 0) {
                const u32 old = atomicAdd(&g_bar[t], 1u);
                const u32 target = (old & ~127u) + 128u;
                while (*(volatile u32*)&g_bar[t] < target) { }
                __threadfence();
            }
            __syncthreads();
        }
    }
}

// ---------------------------------------------------------------------------
extern "C" void kernel_launch(void* const* d_in, const int* in_sizes, int n_in,
                              void* d_out, int out_size) {
    (void)in_sizes; (void)n_in; (void)out_size;
    const float* x  = (const float*)d_in[0];
    const float* a0 = (const float*)d_in[1];
    const float* c0 = (const float*)d_in[2];
    const float* wc = (const float*)d_in[3];
    const float* wu = (const float*)d_in[4];
    const float* wf = (const float*)d_in[5];
    const float* wo = (const float*)d_in[6];
    const float* bc = (const float*)d_in[7];
    const float* bu = (const float*)d_in[8];
    const float* bf = (const float*)d_in[9];
    const float* bo = (const float*)d_in[10];
    float* out = (float*)d_out;

    static int smem_set = 0;
    if (!smem_set) {
        cudaFuncSetAttribute(lstm_persist,
                             cudaFuncAttributeMaxDynamicSharedMemorySize,
                             SMEM_U64 * 8);
        smem_set = 1;
    }

    // Phase 1: x-projection for all timesteps
    dim3 g1(32, TT);
    gx_kernel<<<g1, 256>>>(x, wc, wu, wf, wo, bc, bu, bf, bo);

    // Phase 2: persistent recurrence (all 128 CTAs co-resident)
    lstm_persist<<<NCTA, 256, SMEM_U64 * 8>>>(a0, c0, wc, wu, wf, wo, out);
}

// round 9
// speedup vs baseline: 1.9952x; 1.5392x over previous
#include <cuda_runtime.h>
#include <cuda_bf16.h>
#include <stdint.h>
#include <math.h>

// Problem sizes (fixed)
#define BB   64
#define TT   512
#define EE   1024
#define HH   1024
#define NG   4096
#define AF_ELEMS (64ULL*512ULL*1024ULL)
#define NCTA 128

typedef unsigned long long u64;
typedef unsigned int u32;

// Static device scratch (allocation-free)
__device__ float g_gx[(size_t)TT * BB * NG];        // 512 MB: GX[t][b][n]
__device__ u64   g_a2[2][BB * 512];                 // a state, double-buffered
__device__ u32   g_bar[TT];                         // monotonic barrier counters
__device__ __nv_bfloat16 g_xhi[(size_t)BB*TT*EE];   // 64 MB
__device__ __nv_bfloat16 g_xlo[(size_t)BB*TT*EE];   // 64 MB
__device__ __nv_bfloat16 g_whi[(size_t)NG*HH];      // 8 MB   [g*1024+n][k]
__device__ __nv_bfloat16 g_wlo[(size_t)NG*HH];      // 8 MB

__device__ __forceinline__ void fma2(u64& d, u64 a, u64 b) {
    asm("fma.rn.f32x2 %0, %1, %2, %0;" : "+l"(d) : "l"(a), "l"(b));
}
__device__ __forceinline__ u64 addf2(u64 a, u64 b) {
    u64 r; asm("add.rn.f32x2 %0, %1, %2;" : "=l"(r) : "l"(a), "l"(b)); return r;
}
__device__ __forceinline__ float2 upk(u64 v) {
    float2 f; asm("mov.b64 {%0, %1}, %2;" : "=f"(f.x), "=f"(f.y) : "l"(v)); return f;
}
__device__ __forceinline__ float sigf(float x) { return 1.0f / (1.0f + expf(-x)); }
__device__ __forceinline__ u32 smem_u32(const void* p) {
    u32 a; asm("{ .reg .u64 t; cvta.to.shared.u64 t, %1; cvt.u32.u64 %0, t; }"
               : "=r"(a) : "l"(p));
    return a;
}
#define STS128(a, x, y, z, w) asm volatile("st.shared.v4.b32 [%0], {%1,%2,%3,%4};" :: "r"(a), "r"(x), "r"(y), "r"(z), "r"(w) : "memory")
#define LDM4(d, a) asm volatile("ldmatrix.sync.aligned.m8n8.x4.shared.b16 {%0,%1,%2,%3}, [%4];" \
    : "=r"((d)[0]), "=r"((d)[1]), "=r"((d)[2]), "=r"((d)[3]) : "r"(a))
#define MMA16816(c, a, b0v, b1v) asm volatile( \
    "mma.sync.aligned.m16n8k16.row.col.f32.bf16.bf16.f32 " \
    "{%0,%1,%2,%3}, {%4,%5,%6,%7}, {%8,%9}, {%0,%1,%2,%3};" \
    : "+f"((c)[0]), "+f"((c)[1]), "+f"((c)[2]), "+f"((c)[3]) \
    : "r"((a)[0]), "r"((a)[1]), "r"((a)[2]), "r"((a)[3]), "r"(b0v), "r"(b1v))

// ---------------------------------------------------------------------------
// Split kernel: fp32 -> (bf16 hi, bf16 lo) for X and the x-part of W.
// ---------------------------------------------------------------------------
#define NX4 8388608   // X float4 count (64*512*1024/4)
#define NW4 1048576   // W float4 count (4096*1024/4)

__global__ __launch_bounds__(256) void split_kernel(
    const float* __restrict__ x,
    const float* __restrict__ wc, const float* __restrict__ wu,
    const float* __restrict__ wf, const float* __restrict__ wo)
{
    const size_t i = (size_t)blockIdx.x * 256 + threadIdx.x;
    const float* src;
    __nv_bfloat162* dh;
    __nv_bfloat162* dl;
    if (i < NX4) {
        src = x + i * 4;
        dh = ((__nv_bfloat162*)g_xhi) + i * 2;
        dl = ((__nv_bfloat162*)g_xlo) + i * 2;
    } else if (i < NX4 + NW4) {
        const size_t j = i - NX4;
        const size_t e = j * 4;
        const int ng = (int)(e >> 10), k = (int)(e & 1023);
        const int g = ng >> 10, n = ng & 1023;
        const float* wg = (g == 0) ? wc : (g == 1) ? wu : (g == 2) ? wf : wo;
        src = wg + (size_t)n * 2048 + 1024 + k;
        dh = ((__nv_bfloat162*)g_whi) + j * 2;
        dl = ((__nv_bfloat162*)g_wlo) + j * 2;
    } else return;

    const float4 v = *(const float4*)src;
    __nv_bfloat16 h0 = __float2bfloat16_rn(v.x);
    __nv_bfloat16 h1 = __float2bfloat16_rn(v.y);
    __nv_bfloat16 h2 = __float2bfloat16_rn(v.z);
    __nv_bfloat16 h3 = __float2bfloat16_rn(v.w);
    __nv_bfloat16 l0 = __float2bfloat16_rn(v.x - __bfloat162float(h0));
    __nv_bfloat16 l1 = __float2bfloat16_rn(v.y - __bfloat162float(h1));
    __nv_bfloat16 l2 = __float2bfloat16_rn(v.z - __bfloat162float(h2));
    __nv_bfloat16 l3 = __float2bfloat16_rn(v.w - __bfloat162float(h3));
    __nv_bfloat162 p;
    p.x = h0; p.y = h1; dh[0] = p;
    p.x = h2; p.y = h3; dh[1] = p;
    p.x = l0; p.y = l1; dl[0] = p;
    p.x = l2; p.y = l3; dl[1] = p;
}

// ---------------------------------------------------------------------------
// Phase 1: split-bf16 GEMM via mma.sync (m16n8k16, HMMA path, base sm_103).
//   C[m][n] = X[m][:] . W[n][:],  m = b*512 + t (32768), n (4096).
//   CTA 128x128, 8 warps (2m x 4n), warp tile 64x32, BK=32.
//   D += Ahi*Bhi + Ahi*Blo + Alo*Bhi  (fp32 accum; lo*lo dropped).
//   SMEM rows padded to 80B (conflict-free for 8x16B ldmatrix gathers).
//   B stored [n][k]: matches col-major B fragment with plain ldmatrix.
// ---------------------------------------------------------------------------
__global__ __launch_bounds__(256) void gx_mma(
    const float* __restrict__ bc, const float* __restrict__ bu,
    const float* __restrict__ bf, const float* __restrict__ bo)
{
    __shared__ __align__(16) __nv_bfloat16 sAh[128 * 40];
    __shared__ __align__(16) __nv_bfloat16 sAl[128 * 40];
    __shared__ __align__(16) __nv_bfloat16 sBh[128 * 40];
    __shared__ __align__(16) __nv_bfloat16 sBl[128 * 40];
    __shared__ float s_bias[128];

    const int tid = threadIdx.x, lane = tid & 31, wid = tid >> 5;
    const int nbase = blockIdx.x * 128;
    const int mbase = blockIdx.y * 128;
    const int wm = (wid >> 2) * 64;
    const int wn = (wid & 3) * 32;
    const int q = lane >> 3, r8 = lane & 7;

    if (tid < 128) {
        const int g = nbase >> 10;
        const float* bg = (g == 0) ? bc : (g == 1) ? bu : (g == 2) ? bf : bo;
        s_bias[tid] = bg[(nbase & 1023) + tid];
    }

    const u32 aAh = smem_u32(sAh), aAl = smem_u32(sAl);
    const u32 aBh = smem_u32(sBh), aBl = smem_u32(sBl);
    // ldmatrix per-lane base offsets (bytes), row stride 80B
    const u32 arb = (u32)((wm + (q & 1) * 8 + r8) * 80 + (q >> 1) * 16);
    const u32 brb = (u32)((wn + (q >> 1) * 8 + r8) * 80 + (q & 1) * 16);

    // Loader mapping: 256 threads, rows lrow & lrow+64, 16B per row-quarter
    const int lrow = tid >> 2, lkq = tid & 3;
    const __nv_bfloat16* pAh = g_xhi + (size_t)(mbase + lrow) * 1024 + lkq * 8;
    const __nv_bfloat16* pAl = g_xlo + (size_t)(mbase + lrow) * 1024 + lkq * 8;
    const __nv_bfloat16* pBh = g_whi + (size_t)(nbase + lrow) * 1024 + lkq * 8;
    const __nv_bfloat16* pBl = g_wlo + (size_t)(nbase + lrow) * 1024 + lkq * 8;
    const u32 sso = (u32)(lrow * 80 + lkq * 16);

    float C[4][4][4];
    #pragma unroll
    for (int mf = 0; mf < 4; mf++)
        #pragma unroll
        for (int nf = 0; nf < 4; nf++)
            #pragma unroll
            for (int e = 0; e < 4; e++) C[mf][nf][e] = 0.0f;

    for (int k0 = 0; k0 < 1024; k0 += 32) {
        const uint4 va0 = *(const uint4*)(pAh + k0);
        const uint4 va1 = *(const uint4*)(pAh + 64 * 1024 + k0);
        const uint4 va2 = *(const uint4*)(pAl + k0);
        const uint4 va3 = *(const uint4*)(pAl + 64 * 1024 + k0);
        const uint4 vb0 = *(const uint4*)(pBh + k0);
        const uint4 vb1 = *(const uint4*)(pBh + 64 * 1024 + k0);
        const uint4 vb2 = *(const uint4*)(pBl + k0);
        const uint4 vb3 = *(const uint4*)(pBl + 64 * 1024 + k0);
        __syncthreads();   // previous chunk's compute done
        STS128(aAh + sso,        va0.x, va0.y, va0.z, va0.w);
        STS128(aAh + sso + 5120, va1.x, va1.y, va1.z, va1.w);
        STS128(aAl + sso,        va2.x, va2.y, va2.z, va2.w);
        STS128(aAl + sso + 5120, va3.x, va3.y, va3.z, va3.w);
        STS128(aBh + sso,        vb0.x, vb0.y, vb0.z, vb0.w);
        STS128(aBh + sso + 5120, vb1.x, vb1.y, vb1.z, vb1.w);
        STS128(aBl + sso,        vb2.x, vb2.y, vb2.z, vb2.w);
        STS128(aBl + sso + 5120, vb3.x, vb3.y, vb3.z, vb3.w);
        __syncthreads();

        #pragma unroll
        for (int ks = 0; ks < 2; ks++) {
            u32 ah[4][4], al[4][4], bh[2][4], bl[2][4];
            #pragma unroll
            for (int mf = 0; mf < 4; mf++) {
                LDM4(ah[mf], aAh + arb + mf * 1280 + ks * 32);
                LDM4(al[mf], aAl + arb + mf * 1280 + ks * 32);
            }
            #pragma unroll
            for (int bg = 0; bg < 2; bg++) {
                LDM4(bh[bg], aBh + brb + bg * 1280 + ks * 32);
                LDM4(bl[bg], aBl + brb + bg * 1280 + ks * 32);
            }
            #pragma unroll
            for (int mf = 0; mf < 4; mf++)
                #pragma unroll
                for (int nf = 0; nf < 4; nf++) {
                    const int bg = nf >> 1, o = (nf & 1) * 2;
                    MMA16816(C[mf][nf], ah[mf], bh[bg][o], bh[bg][o + 1]);
                    MMA16816(C[mf][nf], ah[mf], bl[bg][o], bl[bg][o + 1]);
                    MMA16816(C[mf][nf], al[mf], bh[bg][o], bh[bg][o + 1]);
                }
        }
    }

    // Epilogue: C frag (mf,nf): rows m0=.., m0+8; cols n = wn+nf*8+t2*2 (+1)
    const int g2 = lane >> 2, t2 = lane & 3;
    #pragma unroll
    for (int mf = 0; mf < 4; mf++) {
        const int m0 = mbase + wm + mf * 16 + g2;
        const int b  = m0 >> 9;
        const int t0 = m0 & 511;
        #pragma unroll
        for (int nf = 0; nf < 4; nf++) {
            const int nloc = wn + nf * 8 + t2 * 2;
            float2 v0, v1;
            v0.x = C[mf][nf][0] + s_bias[nloc];
            v0.y = C[mf][nf][1] + s_bias[nloc + 1];
            v1.x = C[mf][nf][2] + s_bias[nloc];
            v1.y = C[mf][nf][3] + s_bias[nloc + 1];
            *(float2*)(g_gx + ((size_t)t0 * BB + b) * NG + nbase + nloc) = v0;
            *(float2*)(g_gx + ((size_t)(t0 + 8) * BB + b) * NG + nbase + nloc) = v1;
        }
    }
}

// ---------------------------------------------------------------------------
// Phase 2: PERSISTENT recurrence kernel (validated R3 core).
//   GX now [t][b][n]: staged per-step into SMEM with coalesced loads
//   (thread (b,gate) loads 8 contiguous floats), stride-33 rows
//   (conflict-free stores AND epilogue reads).
// SMEM (u64 units): [0,16384) weights; [16384,24704) a-bufs; [24704,25760) gx
// ---------------------------------------------------------------------------
#define SMEM_U64 25760
#define ABUF(half, par) (16384 + ((half)*2 + (par)) * 2080)

__global__ __launch_bounds__(256, 1) void lstm_persist(
    const float* __restrict__ a0, const float* __restrict__ c0,
    const float* __restrict__ wc, const float* __restrict__ wu,
    const float* __restrict__ wf, const float* __restrict__ wo,
    float* __restrict__ out)
{
    extern __shared__ u64 sm[];
    u64* ws2 = sm;
    float* s_gx = (float*)(sm + 24704);   // [b][33] floats

    const int tid   = threadIdx.x;
    const int lane  = tid & 31;
    const int wid   = tid >> 5;
    const int j     = wid & 3;
    const int khalf = wid >> 2;
    const int hbase = blockIdx.x * 8;
    const int b0 = lane, b1 = lane + 32;
    const int h0 = hbase + j * 2;

    for (int idx = tid; idx < 32 * 512; idx += 256) {
        const int r = idx >> 9, k2 = idx & 511;
        const int g = r >> 3, hh = r & 7;
        const float* wsel = (g == 0) ? wc : (g == 1) ? wu : (g == 2) ? wf : wo;
        ws2[idx] = ((const u64*)(wsel + (size_t)(hbase + hh) * 2048))[k2];
    }

    float creg[2][2];
    if (khalf == 0) {
        #pragma unroll
        for (int h2 = 0; h2 < 2; h2++) {
            creg[h2][0] = c0[b0 * HH + h0 + h2];
            creg[h2][1] = c0[b1 * HH + h0 + h2];
        }
    }

    const u64* wrp[8];
    #pragma unroll
    for (int r = 0; r < 8; r++) {
        const int g = r >> 1, h2 = r & 1;
        wrp[r] = ws2 + (size_t)(g * 8 + j * 2 + h2) * 512 + khalf * 256;
    }
    // GX stage mapping: thread -> (b, gate), 8 contiguous floats
    const int sgb = tid >> 2, sgg = tid & 3;
    __syncthreads();

    for (int t = 0; t < TT; t++) {
        const u64* asrc = (t == 0) ? (const u64*)a0 : g_a2[t & 1];

        // ---- stage GX[t] tile: coalesced 32B per thread -> smem ----
        {
            const float* src = g_gx + (size_t)t * BB * NG
                             + (size_t)sgb * NG + sgg * 1024 + hbase;
            const float4 v0 = __ldcs((const float4*)src);
            const float4 v1 = __ldcs((const float4*)(src + 4));
            float* dst = s_gx + sgb * 33 + sgg * 8;
            dst[0] = v0.x; dst[1] = v0.y; dst[2] = v0.z; dst[3] = v0.w;
            dst[4] = v1.x; dst[5] = v1.y; dst[6] = v1.z; dst[7] = v1.w;
        }

        u64 stage[16];
        #pragma unroll
        for (int v = 0; v < 16; v++) {
            const int idx = tid + v * 256;
            const int k2c = idx & 31, b = (idx >> 5) & 63, half = idx >> 11;
            stage[v] = asrc[(size_t)b * 512 + half * 256 + k2c];
        }
        #pragma unroll
        for (int v = 0; v < 16; v++) {
            const int idx = tid + v * 256;
            const int k2c = idx & 31, b = (idx >> 5) & 63, half = idx >> 11;
            sm[ABUF(half, 0) + k2c * 65 + b] = stage[v];
        }
        #pragma unroll
        for (int v = 0; v < 16; v++) {
            const int idx = tid + v * 256;
            const int k2c = idx & 31, b = (idx >> 5) & 63, half = idx >> 11;
            stage[v] = asrc[(size_t)b * 512 + half * 256 + 32 + k2c];
        }
        __syncthreads();

        u64 acc[8][2];
        #pragma unroll
        for (int r = 0; r < 8; r++) { acc[r][0] = 0ULL; acc[r][1] = 0ULL; }

        for (int i = 0; i < 8; i++) {
            if (i < 7) {
                #pragma unroll
                for (int v = 0; v < 16; v++) {
                    const int idx = tid + v * 256;
                    const int k2c = idx & 31, b = (idx >> 5) & 63, half = idx >> 11;
                    sm[ABUF(half, (i + 1) & 1) + k2c * 65 + b] = stage[v];
                }
            }
            if (i < 6) {
                #pragma unroll
                for (int v = 0; v < 16; v++) {
                    const int idx = tid + v * 256;
                    const int k2c = idx & 31, b = (idx >> 5) & 63, half = idx >> 11;
                    stage[v] = asrc[(size_t)b * 512 + half * 256 + (i + 2) * 32 + k2c];
                }
            }
            const u64* ab2 = sm + ABUF(khalf, i & 1);
            const int koff = i * 32;
            #pragma unroll
            for (int qq = 0; qq < 16; qq++) {
                const int k2 = 2 * qq;
                const u64 a00 = ab2[k2 * 65 + b0];
                const u64 a01 = ab2[k2 * 65 + b1];
                const u64 a10 = ab2[(k2 + 1) * 65 + b0];
                const u64 a11 = ab2[(k2 + 1) * 65 + b1];
                #pragma unroll
                for (int r = 0; r < 8; r++) {
                    const ulonglong2 wv = *(const ulonglong2*)&wrp[r][koff + k2];
                    fma2(acc[r][0], a00, wv.x);
                    fma2(acc[r][1], a01, wv.x);
                    fma2(acc[r][0], a10, wv.y);
                    fma2(acc[r][1], a11, wv.y);
                }
            }
            __syncthreads();
        }

        u64* red = sm + 16384;
        if (khalf == 1) {
            #pragma unroll
            for (int r = 0; r < 8; r++) {
                red[(j * 32 + lane) * 16 + r * 2 + 0] = acc[r][0];
                red[(j * 32 + lane) * 16 + r * 2 + 1] = acc[r][1];
            }
        }
        __syncthreads();

        if (khalf == 0) {
            float pre[4][2][2];
            #pragma unroll
            for (int r = 0; r < 8; r++) {
                const int g = r >> 1, h2 = r & 1;
                #pragma unroll
                for (int bi = 0; bi < 2; bi++) {
                    const u64 s = addf2(acc[r][bi],
                                        red[(j * 32 + lane) * 16 + r * 2 + bi]);
                    const float2 v = upk(s);
                    const int bsel = bi ? b1 : b0;
                    pre[g][h2][bi] = v.x + v.y
                                   + s_gx[bsel * 33 + g * 8 + j * 2 + h2];
                }
            }
            float a1[2][2], c1[2][2];
            #pragma unroll
            for (int h2 = 0; h2 < 2; h2++)
                #pragma unroll
                for (int bi = 0; bi < 2; bi++) {
                    const float cand = tanhf(pre[0][h2][bi]);
                    const float gu   = sigf(pre[1][h2][bi]);
                    const float gf   = sigf(pre[2][h2][bi]);
                    const float go   = sigf(pre[3][h2][bi]);
                    const float cc   = gu * cand + gf * creg[h2][bi];
                    c1[h2][bi] = cc;
                    a1[h2][bi] = go * tanhf(cc);
                    creg[h2][bi] = cc;
                }
            const int bs[2] = {b0, b1};
            #pragma unroll
            for (int bi = 0; bi < 2; bi++) {
                const int b = bs[bi];
                float2 av; av.x = a1[0][bi]; av.y = a1[1][bi];
                *(float2*)(out + (size_t)b * (TT * HH) + (size_t)t * HH + h0) = av;
                *(float2*)&g_a2[(t + 1) & 1][(size_t)b * 512 + (h0 >> 1)] = av;
                if (t == TT - 1) {
                    *(float2*)(out + AF_ELEMS + (size_t)b * HH + h0) = av;
                    float2 cv; cv.x = c1[0][bi]; cv.y = c1[1][bi];
                    *(float2*)(out + AF_ELEMS + (size_t)BB * HH + (size_t)b * HH + h0) = cv;
                }
            }
        }

        if (t < TT - 1) {
            __threadfence();
            __syncthreads();
            if (tid == 0) {
                const u32 old = atomicAdd(&g_bar[t], 1u);
                const u32 target = (old & ~127u) + 128u;
                while (*(volatile u32*)&g_bar[t] < target) { }
                __threadfence();
            }
            __syncthreads();
        }
    }
}

// ---------------------------------------------------------------------------
extern "C" void kernel_launch(void* const* d_in, const int* in_sizes, int n_in,
                              void* d_out, int out_size) {
    (void)in_sizes; (void)n_in; (void)out_size;
    const float* x  = (const float*)d_in[0];
    const float* a0 = (const float*)d_in[1];
    const float* c0 = (const float*)d_in[2];
    const float* wc = (const float*)d_in[3];
    const float* wu = (const float*)d_in[4];
    const float* wf = (const float*)d_in[5];
    const float* wo = (const float*)d_in[6];
    const float* bc = (const float*)d_in[7];
    const float* bu = (const float*)d_in[8];
    const float* bf = (const float*)d_in[9];
    const float* bo = (const float*)d_in[10];
    float* out = (float*)d_out;

    static int attr_set = 0;
    if (!attr_set) {
        cudaFuncSetAttribute(lstm_persist,
                             cudaFuncAttributeMaxDynamicSharedMemorySize,
                             SMEM_U64 * 8);
        attr_set = 1;
    }

    // Phase 0: split fp32 -> bf16 hi/lo
    split_kernel<<<(NX4 + NW4 + 255) / 256, 256>>>(x, wc, wu, wf, wo);

    // Phase 1: HMMA x-projection (GX), grid = (n-tiles, m-tiles)
    dim3 g1(32, 256);
    gx_mma<<<g1, 256>>>(bc, bu, bf, bo);

    // Phase 2: persistent recurrence
    lstm_persist<<<NCTA, 256, SMEM_U64 * 8>>>(a0, c0, wc, wu, wf, wo, out);
}

// round 11
// speedup vs baseline: 3.1390x; 1.5732x over previous
#include <cuda_runtime.h>
#include <cuda_bf16.h>
#include <stdint.h>
#include <math.h>

// Problem sizes (fixed)
#define BB   64
#define TT   512
#define EE   1024
#define HH   1024
#define NG   4096
#define AF_ELEMS (64ULL*512ULL*1024ULL)
#define NCTA 128

typedef unsigned long long u64;
typedef unsigned int u32;

// Static device scratch (allocation-free)
__device__ float g_gx[(size_t)TT * BB * NG];        // 512 MB: GX[t][b][n]
__device__ __nv_bfloat16 g_abf[2][2][BB][HH];       // a state bf16 hi/lo, par-buffered
__device__ u32   g_bar[TT];                         // monotonic barrier counters
__device__ u32   g_bar_pro;                         // prologue barrier counter
__device__ __nv_bfloat16 g_xhi[(size_t)BB*TT*EE];   // 64 MB
__device__ __nv_bfloat16 g_xlo[(size_t)BB*TT*EE];   // 64 MB
__device__ __nv_bfloat16 g_whi[(size_t)NG*HH];      // 8 MB   [g*1024+n][k]
__device__ __nv_bfloat16 g_wlo[(size_t)NG*HH];      // 8 MB

__device__ __forceinline__ float sigf(float x) { return 1.0f / (1.0f + expf(-x)); }
__device__ __forceinline__ u32 smem_u32(const void* p) {
    u32 a; asm("{ .reg .u64 t; cvta.to.shared.u64 t, %1; cvt.u32.u64 %0, t; }"
               : "=r"(a) : "l"(p));
    return a;
}
__device__ __forceinline__ u32 pkbf2(__nv_bfloat16 a, __nv_bfloat16 b) {
    __nv_bfloat162 t; t.x = a; t.y = b;
    return *(u32*)&t;
}
#define STS128(a, x, y, z, w) asm volatile("st.shared.v4.b32 [%0], {%1,%2,%3,%4};" :: "r"(a), "r"(x), "r"(y), "r"(z), "r"(w) : "memory")
#define LDM4(d, a) asm volatile("ldmatrix.sync.aligned.m8n8.x4.shared.b16 {%0,%1,%2,%3}, [%4];" \
    : "=r"((d)[0]), "=r"((d)[1]), "=r"((d)[2]), "=r"((d)[3]) : "r"(a))
#define MMA16816(c, a, b0v, b1v) asm volatile( \
    "mma.sync.aligned.m16n8k16.row.col.f32.bf16.bf16.f32 " \
    "{%0,%1,%2,%3}, {%4,%5,%6,%7}, {%8,%9}, {%0,%1,%2,%3};" \
    : "+f"((c)[0]), "+f"((c)[1]), "+f"((c)[2]), "+f"((c)[3]) \
    : "r"((a)[0]), "r"((a)[1]), "r"((a)[2]), "r"((a)[3]), "r"(b0v), "r"(b1v))

// ---------------------------------------------------------------------------
// Split kernel (validated R9): fp32 -> (bf16 hi, bf16 lo) for X and x-part W.
// ---------------------------------------------------------------------------
#define NX4 8388608
#define NW4 1048576

__global__ __launch_bounds__(256) void split_kernel(
    const float* __restrict__ x,
    const float* __restrict__ wc, const float* __restrict__ wu,
    const float* __restrict__ wf, const float* __restrict__ wo)
{
    const size_t i = (size_t)blockIdx.x * 256 + threadIdx.x;
    const float* src;
    __nv_bfloat162* dh;
    __nv_bfloat162* dl;
    if (i < NX4) {
        src = x + i * 4;
        dh = ((__nv_bfloat162*)g_xhi) + i * 2;
        dl = ((__nv_bfloat162*)g_xlo) + i * 2;
    } else if (i < NX4 + NW4) {
        const size_t j = i - NX4;
        const size_t e = j * 4;
        const int ng = (int)(e >> 10), k = (int)(e & 1023);
        const int g = ng >> 10, n = ng & 1023;
        const float* wg = (g == 0) ? wc : (g == 1) ? wu : (g == 2) ? wf : wo;
        src = wg + (size_t)n * 2048 + 1024 + k;
        dh = ((__nv_bfloat162*)g_whi) + j * 2;
        dl = ((__nv_bfloat162*)g_wlo) + j * 2;
    } else return;

    const float4 v = *(const float4*)src;
    __nv_bfloat16 h0 = __float2bfloat16_rn(v.x);
    __nv_bfloat16 h1 = __float2bfloat16_rn(v.y);
    __nv_bfloat16 h2 = __float2bfloat16_rn(v.z);
    __nv_bfloat16 h3 = __float2bfloat16_rn(v.w);
    __nv_bfloat16 l0 = __float2bfloat16_rn(v.x - __bfloat162float(h0));
    __nv_bfloat16 l1 = __float2bfloat16_rn(v.y - __bfloat162float(h1));
    __nv_bfloat16 l2 = __float2bfloat16_rn(v.z - __bfloat162float(h2));
    __nv_bfloat16 l3 = __float2bfloat16_rn(v.w - __bfloat162float(h3));
    __nv_bfloat162 p;
    p.x = h0; p.y = h1; dh[0] = p;
    p.x = h2; p.y = h3; dh[1] = p;
    p.x = l0; p.y = l1; dl[0] = p;
    p.x = l2; p.y = l3; dl[1] = p;
}

// ---------------------------------------------------------------------------
// Phase 1 (validated R9): split-bf16 GEMM via mma.sync.
// ---------------------------------------------------------------------------
__global__ __launch_bounds__(256) void gx_mma(
    const float* __restrict__ bc, const float* __restrict__ bu,
    const float* __restrict__ bf, const float* __restrict__ bo)
{
    __shared__ __align__(16) __nv_bfloat16 sAh[128 * 40];
    __shared__ __align__(16) __nv_bfloat16 sAl[128 * 40];
    __shared__ __align__(16) __nv_bfloat16 sBh[128 * 40];
    __shared__ __align__(16) __nv_bfloat16 sBl[128 * 40];
    __shared__ float s_bias[128];

    const int tid = threadIdx.x, lane = tid & 31, wid = tid >> 5;
    const int nbase = blockIdx.x * 128;
    const int mbase = blockIdx.y * 128;
    const int wm = (wid >> 2) * 64;
    const int wn = (wid & 3) * 32;
    const int q = lane >> 3, r8 = lane & 7;

    if (tid < 128) {
        const int g = nbase >> 10;
        const float* bg = (g == 0) ? bc : (g == 1) ? bu : (g == 2) ? bf : bo;
        s_bias[tid] = bg[(nbase & 1023) + tid];
    }

    const u32 aAh = smem_u32(sAh), aAl = smem_u32(sAl);
    const u32 aBh = smem_u32(sBh), aBl = smem_u32(sBl);
    const u32 arb = (u32)((wm + (q & 1) * 8 + r8) * 80 + (q >> 1) * 16);
    const u32 brb = (u32)((wn + (q >> 1) * 8 + r8) * 80 + (q & 1) * 16);

    const int lrow = tid >> 2, lkq = tid & 3;
    const __nv_bfloat16* pAh = g_xhi + (size_t)(mbase + lrow) * 1024 + lkq * 8;
    const __nv_bfloat16* pAl = g_xlo + (size_t)(mbase + lrow) * 1024 + lkq * 8;
    const __nv_bfloat16* pBh = g_whi + (size_t)(nbase + lrow) * 1024 + lkq * 8;
    const __nv_bfloat16* pBl = g_wlo + (size_t)(nbase + lrow) * 1024 + lkq * 8;
    const u32 sso = (u32)(lrow * 80 + lkq * 16);

    float C[4][4][4];
    #pragma unroll
    for (int mf = 0; mf < 4; mf++)
        #pragma unroll
        for (int nf = 0; nf < 4; nf++)
            #pragma unroll
            for (int e = 0; e < 4; e++) C[mf][nf][e] = 0.0f;

    for (int k0 = 0; k0 < 1024; k0 += 32) {
        const uint4 va0 = *(const uint4*)(pAh + k0);
        const uint4 va1 = *(const uint4*)(pAh + 64 * 1024 + k0);
        const uint4 va2 = *(const uint4*)(pAl + k0);
        const uint4 va3 = *(const uint4*)(pAl + 64 * 1024 + k0);
        const uint4 vb0 = *(const uint4*)(pBh + k0);
        const uint4 vb1 = *(const uint4*)(pBh + 64 * 1024 + k0);
        const uint4 vb2 = *(const uint4*)(pBl + k0);
        const uint4 vb3 = *(const uint4*)(pBl + 64 * 1024 + k0);
        __syncthreads();
        STS128(aAh + sso,        va0.x, va0.y, va0.z, va0.w);
        STS128(aAh + sso + 5120, va1.x, va1.y, va1.z, va1.w);
        STS128(aAl + sso,        va2.x, va2.y, va2.z, va2.w);
        STS128(aAl + sso + 5120, va3.x, va3.y, va3.z, va3.w);
        STS128(aBh + sso,        vb0.x, vb0.y, vb0.z, vb0.w);
        STS128(aBh + sso + 5120, vb1.x, vb1.y, vb1.z, vb1.w);
        STS128(aBl + sso,        vb2.x, vb2.y, vb2.z, vb2.w);
        STS128(aBl + sso + 5120, vb3.x, vb3.y, vb3.z, vb3.w);
        __syncthreads();

        #pragma unroll
        for (int ks = 0; ks < 2; ks++) {
            u32 ah[4][4], al[4][4], bh[2][4], bl[2][4];
            #pragma unroll
            for (int mf = 0; mf < 4; mf++) {
                LDM4(ah[mf], aAh + arb + mf * 1280 + ks * 32);
                LDM4(al[mf], aAl + arb + mf * 1280 + ks * 32);
            }
            #pragma unroll
            for (int bg = 0; bg < 2; bg++) {
                LDM4(bh[bg], aBh + brb + bg * 1280 + ks * 32);
                LDM4(bl[bg], aBl + brb + bg * 1280 + ks * 32);
            }
            #pragma unroll
            for (int mf = 0; mf < 4; mf++)
                #pragma unroll
                for (int nf = 0; nf < 4; nf++) {
                    const int bg = nf >> 1, o = (nf & 1) * 2;
                    MMA16816(C[mf][nf], ah[mf], bh[bg][o], bh[bg][o + 1]);
                    MMA16816(C[mf][nf], ah[mf], bl[bg][o], bl[bg][o + 1]);
                    MMA16816(C[mf][nf], al[mf], bh[bg][o], bh[bg][o + 1]);
                }
        }
    }

    const int g2 = lane >> 2, t2 = lane & 3;
    #pragma unroll
    for (int mf = 0; mf < 4; mf++) {
        const int m0 = mbase + wm + mf * 16 + g2;
        const int b  = m0 >> 9;
        const int t0 = m0 & 511;
        #pragma unroll
        for (int nf = 0; nf < 4; nf++) {
            const int nloc = wn + nf * 8 + t2 * 2;
            float2 v0, v1;
            v0.x = C[mf][nf][0] + s_bias[nloc];
            v0.y = C[mf][nf][1] + s_bias[nloc + 1];
            v1.x = C[mf][nf][2] + s_bias[nloc];
            v1.y = C[mf][nf][3] + s_bias[nloc + 1];
            *(float2*)(g_gx + ((size_t)t0 * BB + b) * NG + nbase + nloc) = v0;
            *(float2*)(g_gx + ((size_t)(t0 + 8) * BB + b) * NG + nbase + nloc) = v1;
        }
    }
}

// ---------------------------------------------------------------------------
// Phase 2: PERSISTENT recurrence with mma.sync (split bf16, 3 terms).
//   128 CTAs x 256 threads. CTA owns 32 weight rows (4 gates x 8 h), K=1024.
//   Weights bf16 hi/lo resident in SMEM (converted in prologue).
//   a state: g_abf[par][split][b][k] bf16, step-parity double-buffered;
//   epilogue writes a1 as hi/lo. MMA: 8 warps = mw(4) x nw(2), warp 16x16.
//   Per chunk (k=128): a hi/lo staged 64x128 (row stride 272B), weights
//   row stride 2064B; both stride%128==16 -> conflict-free ldmatrix.
// SMEM bytes:
//   [0,66048)        W hi  (32 x 2064)
//   [66048,132096)   W lo
//   [132096,201728)  a bufs: [chunkpar][split] 4 x 64x272
//   [201728,210432)  pre[64][34] f32
//   [210432,218880)  gx [64][33] f32
// ---------------------------------------------------------------------------
#define OFF_WHI 0
#define OFF_WLO 66048
#define OFF_A   132096
#define OFF_PRE 201728
#define OFF_GX  210432
#define SMEM_BYTES 218880
#define ABUFB(cp, sp) (OFF_A + (cp) * 34816 + (sp) * 17408)

__global__ __launch_bounds__(256, 1) void lstm_persist(
    const float* __restrict__ a0, const float* __restrict__ c0,
    const float* __restrict__ wc, const float* __restrict__ wu,
    const float* __restrict__ wf, const float* __restrict__ wo,
    float* __restrict__ out)
{
    extern __shared__ __align__(16) char smc[];
    const u32 sb = smem_u32(smc);
    float* pre_s = (float*)(smc + OFF_PRE);
    float* gx_s  = (float*)(smc + OFF_GX);

    const int tid = threadIdx.x, lane = tid & 31, wid = tid >> 5;
    const int mw = wid & 3, nw = wid >> 2;
    const int hbase = blockIdx.x * 8;

    // ---- prologue: weights -> SMEM bf16 hi/lo (recurrent cols [0,1024)) ----
    #pragma unroll 4
    for (int v = 0; v < 32; v++) {
        const int idx = tid + v * 256;
        const int r = idx >> 8, kq = idx & 255;
        const int g = r >> 3, hh = r & 7;
        const float* wsel = (g == 0) ? wc : (g == 1) ? wu : (g == 2) ? wf : wo;
        const float4 w = *(const float4*)(wsel + (size_t)(hbase + hh) * 2048 + kq * 4);
        __nv_bfloat16 h0 = __float2bfloat16_rn(w.x);
        __nv_bfloat16 h1 = __float2bfloat16_rn(w.y);
        __nv_bfloat16 h2 = __float2bfloat16_rn(w.z);
        __nv_bfloat16 h3 = __float2bfloat16_rn(w.w);
        __nv_bfloat16 l0 = __float2bfloat16_rn(w.x - __bfloat162float(h0));
        __nv_bfloat16 l1 = __float2bfloat16_rn(w.y - __bfloat162float(h1));
        __nv_bfloat16 l2 = __float2bfloat16_rn(w.z - __bfloat162float(h2));
        __nv_bfloat16 l3 = __float2bfloat16_rn(w.w - __bfloat162float(h3));
        u32* ph = (u32*)(smc + OFF_WHI + r * 2064 + kq * 8);
        u32* pl = (u32*)(smc + OFF_WLO + r * 2064 + kq * 8);
        ph[0] = pkbf2(h0, h1); ph[1] = pkbf2(h2, h3);
        pl[0] = pkbf2(l0, l1); pl[1] = pkbf2(l2, l3);
    }

    // ---- prologue: this CTA's slice of a0 -> g_abf[0] hi/lo ----
    {
        const int idx = blockIdx.x * 512 + tid * 2;
        const int b = idx >> 10, h = idx & 1023;
        const float2 v = *(const float2*)(a0 + (size_t)b * 1024 + h);
        __nv_bfloat16 h0 = __float2bfloat16_rn(v.x);
        __nv_bfloat16 h1 = __float2bfloat16_rn(v.y);
        __nv_bfloat16 l0 = __float2bfloat16_rn(v.x - __bfloat162float(h0));
        __nv_bfloat16 l1 = __float2bfloat16_rn(v.y - __bfloat162float(h1));
        *(u32*)&g_abf[0][0][b][h] = pkbf2(h0, h1);
        *(u32*)&g_abf[0][1][b][h] = pkbf2(l0, l1);
    }

    // ---- c-state in registers: thread owns (b_e, 2 h values) ----
    const int b_e = tid & 63, jp = tid >> 6;
    const int h0e = hbase + jp * 2;
    float creg[2];
    creg[0] = c0[b_e * HH + h0e];
    creg[1] = c0[b_e * HH + h0e + 1];

    // ---- prologue grid barrier (monotonic) ----
    __threadfence();
    __syncthreads();
    if (tid == 0) {
        const u32 old = atomicAdd(&g_bar_pro, 1u);
        const u32 target = (old & ~127u) + 128u;
        while (*(volatile u32*)&g_bar_pro < target) { }
        __threadfence();
    }
    __syncthreads();

    // ldmatrix per-lane bases
    const int q = lane >> 3, r8 = lane & 7;
    const u32 a_off = (u32)((mw * 16 + (q & 1) * 8 + r8) * 272 + (q >> 1) * 16);
    const u32 b_off = (u32)((nw * 16 + (q >> 1) * 8 + r8) * 2064 + (q & 1) * 16);

    // staging mapping
    const int sgb = tid >> 2, sgg = tid & 3;

    for (int t = 0; t < TT; t++) {
        const int par = t & 1;
        const __nv_bfloat16* abase = &g_abf[par][0][0][0];

        // ---- stage GX tile (coalesced 32B/thread) ----
        {
            const float* src = g_gx + (size_t)t * BB * NG
                             + (size_t)sgb * NG + sgg * 1024 + hbase;
            const float4 v0 = __ldcs((const float4*)src);
            const float4 v1 = __ldcs((const float4*)(src + 4));
            float* dst = gx_s + sgb * 33 + sgg * 8;
            dst[0] = v0.x; dst[1] = v0.y; dst[2] = v0.z; dst[3] = v0.w;
            dst[4] = v1.x; dst[5] = v1.y; dst[6] = v1.z; dst[7] = v1.w;
        }

        // ---- chunk pipeline: 8 chunks of k=128 ----
        uint4 stg[8];
        #pragma unroll
        for (int v = 0; v < 8; v++) {
            const int sp = v >> 2, idx2 = tid + (v & 3) * 256;
            const int bb = idx2 >> 4, kk = idx2 & 15;
            stg[v] = *(const uint4*)(abase + sp * 65536 + bb * 1024 + kk * 8);
        }
        #pragma unroll
        for (int v = 0; v < 8; v++) {
            const int sp = v >> 2, idx2 = tid + (v & 3) * 256;
            const int bb = idx2 >> 4, kk = idx2 & 15;
            STS128(sb + ABUFB(0, sp) + bb * 272 + kk * 16,
                   stg[v].x, stg[v].y, stg[v].z, stg[v].w);
        }
        #pragma unroll
        for (int v = 0; v < 8; v++) {
            const int sp = v >> 2, idx2 = tid + (v & 3) * 256;
            const int bb = idx2 >> 4, kk = idx2 & 15;
            stg[v] = *(const uint4*)(abase + sp * 65536 + bb * 1024 + 128 + kk * 8);
        }
        __syncthreads();

        float C[2][4];
        #pragma unroll
        for (int nf = 0; nf < 2; nf++)
            #pragma unroll
            for (int e = 0; e < 4; e++) C[nf][e] = 0.0f;

        for (int i = 0; i < 8; i++) {
            if (i < 7) {
                #pragma unroll
                for (int v = 0; v < 8; v++) {
                    const int sp = v >> 2, idx2 = tid + (v & 3) * 256;
                    const int bb = idx2 >> 4, kk = idx2 & 15;
                    STS128(sb + ABUFB((i + 1) & 1, sp) + bb * 272 + kk * 16,
                           stg[v].x, stg[v].y, stg[v].z, stg[v].w);
                }
            }
            if (i < 6) {
                #pragma unroll
                for (int v = 0; v < 8; v++) {
                    const int sp = v >> 2, idx2 = tid + (v & 3) * 256;
                    const int bb = idx2 >> 4, kk = idx2 & 15;
                    stg[v] = *(const uint4*)(abase + sp * 65536 + bb * 1024
                                             + (i + 2) * 128 + kk * 8);
                }
            }
            const u32 ahB = sb + ABUFB(i & 1, 0) + a_off;
            const u32 alB = sb + ABUFB(i & 1, 1) + a_off;
            const u32 bhB = sb + OFF_WHI + b_off + i * 256;
            const u32 blB = sb + OFF_WLO + b_off + i * 256;
            #pragma unroll
            for (int k16 = 0; k16 < 8; k16++) {
                u32 ah[4], al[4], bh[4], bl[4];
                LDM4(ah, ahB + k16 * 32);
                LDM4(al, alB + k16 * 32);
                LDM4(bh, bhB + k16 * 32);
                LDM4(bl, blB + k16 * 32);
                #pragma unroll
                for (int nf = 0; nf < 2; nf++) {
                    const int o = nf * 2;
                    MMA16816(C[nf], ah, bh[o], bh[o + 1]);
                    MMA16816(C[nf], ah, bl[o], bl[o + 1]);
                    MMA16816(C[nf], al, bh[o], bh[o + 1]);
                }
            }
            __syncthreads();
        }

        // ---- fragments -> pre_s[b][r] (r = gate*8+hh), stride 34 ----
        {
            const int g2 = lane >> 2, t2 = lane & 3;
            const int row0 = mw * 16 + g2;
            #pragma unroll
            for (int nf = 0; nf < 2; nf++) {
                const int col = nw * 16 + nf * 8 + t2 * 2;
                float2 v0; v0.x = C[nf][0]; v0.y = C[nf][1];
                float2 v1; v1.x = C[nf][2]; v1.y = C[nf][3];
                *(float2*)&pre_s[row0 * 34 + col] = v0;
                *(float2*)&pre_s[(row0 + 8) * 34 + col] = v1;
            }
        }
        __syncthreads();

        // ---- elementwise LSTM update: thread owns (b_e, h0e..h0e+1) ----
        float a1v[2], c1v[2];
        #pragma unroll
        for (int e = 0; e < 2; e++) {
            const int hh = jp * 2 + e;
            const float p0 = pre_s[b_e * 34 + hh]      + gx_s[b_e * 33 + hh];
            const float p1 = pre_s[b_e * 34 + 8 + hh]  + gx_s[b_e * 33 + 8 + hh];
            const float p2 = pre_s[b_e * 34 + 16 + hh] + gx_s[b_e * 33 + 16 + hh];
            const float p3 = pre_s[b_e * 34 + 24 + hh] + gx_s[b_e * 33 + 24 + hh];
            const float cand = tanhf(p0);
            const float gu   = sigf(p1);
            const float gf   = sigf(p2);
            const float go   = sigf(p3);
            const float cc   = gu * cand + gf * creg[e];
            creg[e] = cc;
            c1v[e] = cc;
            a1v[e] = go * tanhf(cc);
        }
        {
            float2 av; av.x = a1v[0]; av.y = a1v[1];
            *(float2*)(out + (size_t)b_e * (TT * HH) + (size_t)t * HH + h0e) = av;
            __nv_bfloat16 h0 = __float2bfloat16_rn(a1v[0]);
            __nv_bfloat16 h1 = __float2bfloat16_rn(a1v[1]);
            __nv_bfloat16 l0 = __float2bfloat16_rn(a1v[0] - __bfloat162float(h0));
            __nv_bfloat16 l1 = __float2bfloat16_rn(a1v[1] - __bfloat162float(h1));
            const int np = (t + 1) & 1;
            *(u32*)&g_abf[np][0][b_e][h0e] = pkbf2(h0, h1);
            *(u32*)&g_abf[np][1][b_e][h0e] = pkbf2(l0, l1);
            if (t == TT - 1) {
                *(float2*)(out + AF_ELEMS + (size_t)b_e * HH + h0e) = av;
                float2 cv; cv.x = c1v[0]; cv.y = c1v[1];
                *(float2*)(out + AF_ELEMS + (size_t)BB * HH + (size_t)b_e * HH + h0e) = cv;
            }
        }

        // ---- grid barrier (monotonic) ----
        if (t < TT - 1) {
            __threadfence();
            __syncthreads();
            if (tid == 0) {
                const u32 old = atomicAdd(&g_bar[t], 1u);
                const u32 target = (old & ~127u) + 128u;
                while (*(volatile u32*)&g_bar[t] < target) { }
                __threadfence();
            }
            __syncthreads();
        }
    }
}

// ---------------------------------------------------------------------------
extern "C" void kernel_launch(void* const* d_in, const int* in_sizes, int n_in,
                              void* d_out, int out_size) {
    (void)in_sizes; (void)n_in; (void)out_size;
    const float* x  = (const float*)d_in[0];
    const float* a0 = (const float*)d_in[1];
    const float* c0 = (const float*)d_in[2];
    const float* wc = (const float*)d_in[3];
    const float* wu = (const float*)d_in[4];
    const float* wf = (const float*)d_in[5];
    const float* wo = (const float*)d_in[6];
    const float* bc = (const float*)d_in[7];
    const float* bu = (const float*)d_in[8];
    const float* bf = (const float*)d_in[9];
    const float* bo = (const float*)d_in[10];
    float* out = (float*)d_out;

    static int attr_set = 0;
    if (!attr_set) {
        cudaFuncSetAttribute(lstm_persist,
                             cudaFuncAttributeMaxDynamicSharedMemorySize,
                             SMEM_BYTES);
        attr_set = 1;
    }

    // Phase 0: split fp32 -> bf16 hi/lo
    split_kernel<<<(NX4 + NW4 + 255) / 256, 256>>>(x, wc, wu, wf, wo);

    // Phase 1: HMMA x-projection (GX)
    dim3 g1(32, 256);
    gx_mma<<<g1, 256>>>(bc, bu, bf, bo);

    // Phase 2: persistent tensor-core recurrence
    lstm_persist<<<NCTA, 256, SMEM_BYTES>>>(a0, c0, wc, wu, wf, wo, out);
}